// round 1
// baseline (speedup 1.0000x reference)
#include <cuda_runtime.h>
#include <cstring>
#include <cstdint>

typedef unsigned long long ull;

// ---------------- f32x2 packed helpers ----------------
static __device__ __forceinline__ ull pack2(float lo, float hi) {
    float2 t = make_float2(lo, hi);
    ull r; memcpy(&r, &t, 8); return r;
}
static __device__ __forceinline__ float2 unpack2(ull v) {
    float2 t; memcpy(&t, &v, 8); return t;
}
static __device__ __forceinline__ void fma2(ull& d, ull a, ull b, ull c) {
    asm("fma.rn.f32x2 %0, %1, %2, %3;" : "=l"(d) : "l"(a), "l"(b), "l"(c));
}

// ---------------- problem constants ----------------
#define NB 8
#define HH 64
#define WW 64
#define NN (HH*WW)          // 4096
#define VAIN 256
#define VBIN 128
#define VCIN 64
#define VOUT 128

// ---------------- scratch (device globals; no allocs) ----------------
__device__ float g_ha   [(size_t)NB*NN*128];          // relu(W_a1 @ xa), channel-last
__device__ float g_emba [(size_t)NB*NN*128];
__device__ float g_gateb[(size_t)NB*NN*128];
__device__ float g_gatec[(size_t)NB*NN*128];
__device__ float g_hb   [(size_t)NB*16384*128];
__device__ float g_embb [(size_t)NB*16384*128];
__device__ float g_hc   [(size_t)NB*65536*128];
__device__ float g_embc [(size_t)NB*65536*128];
__device__ float g_agg  [(size_t)NB*NN*384];
__device__ float g_y    [(size_t)NB*NN*256];

// ---------------- generic tiled GEMM ----------------
// out[b][m][o] = act( sum_k X[...] * W[o][k] )
// XL==0: X is [B][K][M] (channel-major, e.g. vert_* inputs)
// XL==1: X is [B][M][K] (channel-last intermediates)
// ACT: 0=none, 1=relu, 2=(1-sigmoid)
// OUTCM: write out as [B][O][M] (channel-major) via smem transpose
constexpr int MT = 128, OT = 64, KT = 32;

template<int XL, int ACT, bool OUTCM>
__global__ __launch_bounds__(256)
void gemm_k(const float* __restrict__ X, const float* __restrict__ W,
            float* __restrict__ out, int M, int K, int O)
{
    constexpr int XROW = MT + 4;   // 132 floats/row (16B aligned rows)
    constexpr int WROW = OT + 4;   // 68
    constexpr int SM_MAIN = KT*XROW + KT*WROW;              // 6400 floats
    constexpr int SM_T    = OUTCM ? MT*(OT+1) : 0;          // 8320 floats
    constexpr int SMS     = (SM_T > SM_MAIN) ? SM_T : SM_MAIN;
    __shared__ __align__(16) float sm[SMS];
    float (*Xt)[XROW] = (float(*)[XROW])sm;
    float (*Wt)[WROW] = (float(*)[WROW])(sm + KT*XROW);

    const int tid = threadIdx.x;
    const int tx  = tid & 15;    // o dimension (4 cols each)
    const int ty  = tid >> 4;    // m dimension (8 rows each)
    const int b   = blockIdx.z;
    const int m0  = blockIdx.x * MT;
    const int o0  = blockIdx.y * OT;

    const float* Xb = X + (size_t)b * (size_t)M * (size_t)K;

    ull acc[8][2];
    #pragma unroll
    for (int i = 0; i < 8; i++) { acc[i][0] = 0ull; acc[i][1] = 0ull; }

    for (int k0 = 0; k0 < K; k0 += KT) {
        // ---- load X tile -> Xt[kk][mm] ----
        if (XL == 0) {
            int kk = tid >> 3;            // 0..31
            int mm = (tid & 7) << 4;      // 0,16,..,112
            const float4* src = (const float4*)(Xb + (size_t)(k0 + kk) * M + (m0 + mm));
            float4 v0 = src[0], v1 = src[1], v2 = src[2], v3 = src[3];
            *(float4*)&Xt[kk][mm+ 0] = v0;
            *(float4*)&Xt[kk][mm+ 4] = v1;
            *(float4*)&Xt[kk][mm+ 8] = v2;
            *(float4*)&Xt[kk][mm+12] = v3;
        } else {
            int mm  = tid >> 1;           // 0..127
            int kk0 = (tid & 1) << 4;     // 0 or 16
            const float4* src = (const float4*)(Xb + (size_t)(m0 + mm) * K + (k0 + kk0));
            #pragma unroll
            for (int q = 0; q < 4; q++) {
                float4 v = src[q];
                Xt[kk0 + q*4 + 0][mm] = v.x;
                Xt[kk0 + q*4 + 1][mm] = v.y;
                Xt[kk0 + q*4 + 2][mm] = v.z;
                Xt[kk0 + q*4 + 3][mm] = v.w;
            }
        }
        // ---- load W tile (W is [O][K] row-major) -> Wt[kk][oo] ----
        {
            int oo  = tid >> 2;           // 0..63
            int kk0 = (tid & 3) << 3;     // 0,8,16,24
            const float4* src = (const float4*)(W + (size_t)(o0 + oo) * K + (k0 + kk0));
            #pragma unroll
            for (int q = 0; q < 2; q++) {
                float4 v = src[q];
                Wt[kk0 + q*4 + 0][oo] = v.x;
                Wt[kk0 + q*4 + 1][oo] = v.y;
                Wt[kk0 + q*4 + 2][oo] = v.z;
                Wt[kk0 + q*4 + 3][oo] = v.w;
            }
        }
        __syncthreads();

        #pragma unroll
        for (int kk = 0; kk < KT; kk++) {
            const float4 a0 = *(const float4*)&Xt[kk][ty*8];
            const float4 a1 = *(const float4*)&Xt[kk][ty*8 + 4];
            const ull bp0 = *(const ull*)&Wt[kk][tx*4];
            const ull bp1 = *(const ull*)&Wt[kk][tx*4 + 2];
            ull ad;
            ad = pack2(a0.x, a0.x); fma2(acc[0][0], ad, bp0, acc[0][0]); fma2(acc[0][1], ad, bp1, acc[0][1]);
            ad = pack2(a0.y, a0.y); fma2(acc[1][0], ad, bp0, acc[1][0]); fma2(acc[1][1], ad, bp1, acc[1][1]);
            ad = pack2(a0.z, a0.z); fma2(acc[2][0], ad, bp0, acc[2][0]); fma2(acc[2][1], ad, bp1, acc[2][1]);
            ad = pack2(a0.w, a0.w); fma2(acc[3][0], ad, bp0, acc[3][0]); fma2(acc[3][1], ad, bp1, acc[3][1]);
            ad = pack2(a1.x, a1.x); fma2(acc[4][0], ad, bp0, acc[4][0]); fma2(acc[4][1], ad, bp1, acc[4][1]);
            ad = pack2(a1.y, a1.y); fma2(acc[5][0], ad, bp0, acc[5][0]); fma2(acc[5][1], ad, bp1, acc[5][1]);
            ad = pack2(a1.z, a1.z); fma2(acc[6][0], ad, bp0, acc[6][0]); fma2(acc[6][1], ad, bp1, acc[6][1]);
            ad = pack2(a1.w, a1.w); fma2(acc[7][0], ad, bp0, acc[7][0]); fma2(acc[7][1], ad, bp1, acc[7][1]);
        }
        __syncthreads();
    }

    // ---- epilogue ----
    float c[8][4];
    #pragma unroll
    for (int i = 0; i < 8; i++) {
        float2 lo = unpack2(acc[i][0]);
        float2 hi = unpack2(acc[i][1]);
        c[i][0] = lo.x; c[i][1] = lo.y; c[i][2] = hi.x; c[i][3] = hi.y;
    }
    #pragma unroll
    for (int i = 0; i < 8; i++)
        #pragma unroll
        for (int j = 0; j < 4; j++) {
            if (ACT == 1) c[i][j] = fmaxf(c[i][j], 0.0f);
            else if (ACT == 2) c[i][j] = 1.0f / (1.0f + __expf(c[i][j]));   // 1 - sigmoid(v)
        }

    if (!OUTCM) {
        #pragma unroll
        for (int i = 0; i < 8; i++) {
            float4 v = make_float4(c[i][0], c[i][1], c[i][2], c[i][3]);
            *(float4*)(out + ((size_t)b * M + (m0 + ty*8 + i)) * (size_t)O + o0 + tx*4) = v;
        }
    } else {
        float (*T)[OT + 1] = (float(*)[OT + 1])sm;
        #pragma unroll
        for (int i = 0; i < 8; i++)
            #pragma unroll
            for (int j = 0; j < 4; j++)
                T[ty*8 + i][tx*4 + j] = c[i][j];
        __syncthreads();
        int ol = tid >> 2;              // 0..63
        int mb = (tid & 3) << 5;        // 0,32,64,96
        float* ob = out + ((size_t)b * O + o0 + ol) * (size_t)M + m0 + mb;
        #pragma unroll
        for (int q = 0; q < 8; q++) {
            float4 v = make_float4(T[mb + q*4 + 0][ol], T[mb + q*4 + 1][ol],
                                   T[mb + q*4 + 2][ol], T[mb + q*4 + 3][ol]);
            *(float4*)(ob + q*4) = v;
        }
    }
}

// ---------------- attention (warp per pixel) ----------------
static __device__ __forceinline__ float wsum(float v) {
    #pragma unroll
    for (int o = 16; o > 0; o >>= 1) v += __shfl_xor_sync(0xffffffffu, v, o);
    return v;
}
static __device__ __forceinline__ float sigm(float x) {
    return 1.0f / (1.0f + __expf(-x));
}

__global__ __launch_bounds__(128)
void attend_k(const float* __restrict__ emba, const float* __restrict__ gateb,
              const float* __restrict__ gatec, const float* __restrict__ embb,
              const float* __restrict__ embc, const float* __restrict__ Wab,
              const float* __restrict__ Wac, float* __restrict__ agg)
{
    int gw   = (blockIdx.x * 128 + threadIdx.x) >> 5;   // 0..32767
    int lane = threadIdx.x & 31;
    int b = gw >> 12, n = gw & 4095;
    int h = n >> 6, w = n & 63;
    size_t nb = (size_t)b * NN + n;

    const float* eap = emba + nb * 128;
    float ea[4], gb[4], gc[4];
    float pab = 0.f, pac = 0.f;
    #pragma unroll
    for (int j = 0; j < 4; j++) {
        int cc = lane + 32*j;
        ea[j] = eap[cc];
        gb[j] = gateb[nb*128 + cc];
        gc[j] = gatec[nb*128 + cc];
        pab += Wab[cc] * ea[j];
        pac += Wac[cc] * ea[j];
    }
    float dab = wsum(pab);
    float dac = wsum(pac);

    float* ag = agg + nb * 384;

    // ---- B branch: 4 patches ----
    {
        float eb[4][4], lb[4];
        #pragma unroll
        for (int p = 0; p < 4; p++) {
            int kh = p >> 1, kw = p & 1;
            const float* ep = embb + ((size_t)b*16384 + (size_t)(2*h + kh)*128 + (2*w + kw)) * 128;
            float s = 0.f;
            #pragma unroll
            for (int j = 0; j < 4; j++) {
                int cc = lane + 32*j;
                eb[p][j] = ep[cc];
                s += Wab[128 + cc] * eb[p][j];
            }
            lb[p] = fmaxf(dab + wsum(s), 0.0f);
        }
        float mx = fmaxf(fmaxf(lb[0], lb[1]), fmaxf(lb[2], lb[3]));
        float ssum = 0.f;
        #pragma unroll
        for (int p = 0; p < 4; p++) { lb[p] = __expf(lb[p] - mx); ssum += lb[p]; }
        float inv = 1.0f / ssum;
        #pragma unroll
        for (int j = 0; j < 4; j++) {
            float a = 0.f;
            #pragma unroll
            for (int p = 0; p < 4; p++) a += eb[p][j] * lb[p];
            a *= inv * gb[j];
            ag[lane + 32*j] = sigm(a);
        }
    }

    // ---- C branch: 16 patches ----
    {
        float ec[16][4], lc[16];
        #pragma unroll
        for (int p = 0; p < 16; p++) {
            int kh = p >> 2, kw = p & 3;
            const float* ep = embc + ((size_t)b*65536 + (size_t)(4*h + kh)*256 + (4*w + kw)) * 128;
            float s = 0.f;
            #pragma unroll
            for (int j = 0; j < 4; j++) {
                int cc = lane + 32*j;
                ec[p][j] = ep[cc];
                s += Wac[128 + cc] * ec[p][j];
            }
            lc[p] = fmaxf(dac + wsum(s), 0.0f);
        }
        float mx = lc[0];
        #pragma unroll
        for (int p = 1; p < 16; p++) mx = fmaxf(mx, lc[p]);
        float ssum = 0.f;
        #pragma unroll
        for (int p = 0; p < 16; p++) { lc[p] = __expf(lc[p] - mx); ssum += lc[p]; }
        float inv = 1.0f / ssum;
        #pragma unroll
        for (int j = 0; j < 4; j++) {
            float a = 0.f;
            #pragma unroll
            for (int p = 0; p < 16; p++) a += ec[p][j] * lc[p];
            a *= inv * gc[j];
            ag[128 + lane + 32*j] = sigm(a);
        }
    }

    // ---- emb_a passthrough (sigmoid) ----
    #pragma unroll
    for (int j = 0; j < 4; j++)
        ag[256 + lane + 32*j] = sigm(ea[j]);
}

// ---------------- launch ----------------
extern "C" void kernel_launch(void* const* d_in, const int* in_sizes, int n_in,
                              void* d_out, int out_size)
{
    const float* va   = (const float*)d_in[0];
    const float* vb   = (const float*)d_in[1];
    const float* vc   = (const float*)d_in[2];
    const float* Wa1  = (const float*)d_in[3];
    const float* Wa2  = (const float*)d_in[4];
    const float* Wgb  = (const float*)d_in[5];
    const float* Wgc  = (const float*)d_in[6];
    const float* Wb1  = (const float*)d_in[7];
    const float* Wb2  = (const float*)d_in[8];
    const float* Wc1  = (const float*)d_in[9];
    const float* Wc2  = (const float*)d_in[10];
    const float* Wab  = (const float*)d_in[11];
    const float* Wac  = (const float*)d_in[12];
    const float* Wr1  = (const float*)d_in[13];
    const float* Wr2  = (const float*)d_in[14];
    float* out = (float*)d_out;

    float *ha, *emba, *gateb, *gatec, *hb, *embb, *hc, *embc, *agg, *yb;
    cudaGetSymbolAddress((void**)&ha,    g_ha);
    cudaGetSymbolAddress((void**)&emba,  g_emba);
    cudaGetSymbolAddress((void**)&gateb, g_gateb);
    cudaGetSymbolAddress((void**)&gatec, g_gatec);
    cudaGetSymbolAddress((void**)&hb,    g_hb);
    cudaGetSymbolAddress((void**)&embb,  g_embb);
    cudaGetSymbolAddress((void**)&hc,    g_hc);
    cudaGetSymbolAddress((void**)&embc,  g_embc);
    cudaGetSymbolAddress((void**)&agg,   g_agg);
    cudaGetSymbolAddress((void**)&yb,    g_y);

    dim3 blk(256);
    // emb_a stage
    gemm_k<0,1,false><<<dim3(4096/MT, 128/OT, NB), blk>>>(va, Wa1, ha,    4096, 256, 128);
    gemm_k<0,2,false><<<dim3(4096/MT, 128/OT, NB), blk>>>(va, Wgb, gateb, 4096, 256, 128);
    gemm_k<0,2,false><<<dim3(4096/MT, 128/OT, NB), blk>>>(va, Wgc, gatec, 4096, 256, 128);
    gemm_k<1,0,false><<<dim3(4096/MT, 128/OT, NB), blk>>>(ha, Wa2, emba,  4096, 128, 128);
    // emb_b stage
    gemm_k<0,1,false><<<dim3(16384/MT, 128/OT, NB), blk>>>(vb, Wb1, hb,   16384, 128, 128);
    gemm_k<1,0,false><<<dim3(16384/MT, 128/OT, NB), blk>>>(hb, Wb2, embb, 16384, 128, 128);
    // emb_c stage
    gemm_k<0,1,false><<<dim3(65536/MT, 128/OT, NB), blk>>>(vc, Wc1, hc,   65536,  64, 128);
    gemm_k<1,0,false><<<dim3(65536/MT, 128/OT, NB), blk>>>(hc, Wc2, embc, 65536, 128, 128);
    // attention + gather + sigmoid -> agg [B][N][384]
    attend_k<<<8192, 128>>>(emba, gateb, gatec, embb, embc, Wab, Wac, agg);
    // readout
    gemm_k<1,1,false><<<dim3(4096/MT, 256/OT, NB), blk>>>(agg, Wr1, yb, 4096, 384, 256);
    gemm_k<1,0,true ><<<dim3(4096/MT, 256/OT, NB), blk>>>(yb, Wr2, out, 4096, 256, 256);
}